// round 1
// baseline (speedup 1.0000x reference)
#include <cuda_runtime.h>
#include <cstdint>

#define XS_STRIDE 132   // 128 + 4 pad (words) — conflict-free A-frag loads
#define WS_STRIDE 136   // 128 + 8 pad (words) — conflict-free B-frag loads

__device__ __forceinline__ uint32_t f2tf(float f) {
    uint32_t r;
    asm("cvt.rna.tf32.f32 %0, %1;" : "=r"(r) : "f"(f));
    return r;
}

__device__ __forceinline__ void mma_tf32(float* d,
                                         uint32_t a0, uint32_t a1, uint32_t a2, uint32_t a3,
                                         uint32_t b0, uint32_t b1) {
    asm volatile(
        "mma.sync.aligned.m16n8k8.row.col.f32.tf32.tf32.f32 "
        "{%0,%1,%2,%3}, {%4,%5,%6,%7}, {%8,%9}, {%0,%1,%2,%3};\n"
        : "+f"(d[0]), "+f"(d[1]), "+f"(d[2]), "+f"(d[3])
        : "r"(a0), "r"(a1), "r"(a2), "r"(a3), "r"(b0), "r"(b1));
}

// smem byte offsets
#define OFF_XS   0                         // uint32 tf32, 64 x 132   (33792 B), reused as ctx
#define OFF_QKV  33792                     // float,       3 x 64 x 132 (101376 B)
#define OFF_WS   135168                    // uint32 tf32, 128 x 136  (69632 B)
#define OFF_RV   204800                    // float, 16 residue-valid flags
#define SMEM_BYTES 204864

__global__ __launch_bounds__(256, 1)
void laa_kernel(const float* __restrict__ x, const uint32_t* __restrict__ mask,
                const float* __restrict__ Wq, const float* __restrict__ bq,
                const float* __restrict__ Wk, const float* __restrict__ bk,
                const float* __restrict__ Wv, const float* __restrict__ bv,
                const float* __restrict__ Wo, const float* __restrict__ bo,
                float* __restrict__ out)
{
    extern __shared__ char smem[];
    uint32_t* Xs    = (uint32_t*)(smem + OFF_XS);
    float*    qkv   = (float*)   (smem + OFF_QKV);
    uint32_t* Ws    = (uint32_t*)(smem + OFF_WS);
    float*    resvl = (float*)   (smem + OFF_RV);

    const int tid    = threadIdx.x;
    const int lane   = tid & 31;
    const int warp   = tid >> 5;
    const int gid    = lane >> 2;   // 0..7
    const int tig    = lane & 3;    // 0..3
    const int warp_m = warp >> 2;   // 0..1 (rows 0..31 / 32..63)
    const int warp_n = warp & 3;    // 0..3 (32-col slabs)
    const int row0   = blockIdx.x * 64;

    // ---- load X tile (64x128 fp32) -> Xs as tf32 ----
    #pragma unroll
    for (int i = 0; i < 8; i++) {
        int fi = tid + i * 256;          // 0..2047 float4 slots
        int r  = fi >> 5;                // 32 float4 per row
        int c4 = fi & 31;
        float4 v = *(const float4*)(x + (size_t)(row0 + r) * 128 + c4 * 4);
        uint32_t* dst = Xs + r * XS_STRIDE + c4 * 4;
        dst[0] = f2tf(v.x); dst[1] = f2tf(v.y); dst[2] = f2tf(v.z); dst[3] = f2tf(v.w);
    }

    auto loadW = [&](const float* W) {
        #pragma unroll
        for (int i = 0; i < 16; i++) {
            int fi = tid + i * 256;      // 0..4095 float4 slots
            int r  = fi >> 5;
            int c4 = fi & 31;
            float4 v = *(const float4*)(W + r * 128 + c4 * 4);
            uint32_t* dst = Ws + r * WS_STRIDE + c4 * 4;
            dst[0] = f2tf(v.x); dst[1] = f2tf(v.y); dst[2] = f2tf(v.z); dst[3] = f2tf(v.w);
        }
    };

    // GEMM: acc[2][4][4] = As(64x128, tf32, stride XS_STRIDE) @ Ws(128x128, tf32)
    auto gemm = [&](const uint32_t* As, float acc[2][4][4]) {
        #pragma unroll
        for (int mt = 0; mt < 2; mt++)
            #pragma unroll
            for (int nt = 0; nt < 4; nt++)
                #pragma unroll
                for (int j = 0; j < 4; j++) acc[mt][nt][j] = 0.f;

        const int mb0 = warp_m * 32;
        const int nb0 = warp_n * 32;
        #pragma unroll
        for (int kk = 0; kk < 16; kk++) {
            const int k0 = kk * 8;
            uint32_t a[2][4];
            #pragma unroll
            for (int mt = 0; mt < 2; mt++) {
                const uint32_t* ap = As + (mb0 + mt * 16 + gid) * XS_STRIDE + k0 + tig;
                a[mt][0] = ap[0];
                a[mt][1] = ap[8 * XS_STRIDE];
                a[mt][2] = ap[4];
                a[mt][3] = ap[8 * XS_STRIDE + 4];
            }
            uint32_t b[4][2];
            #pragma unroll
            for (int nt = 0; nt < 4; nt++) {
                const uint32_t* bp = Ws + (k0 + tig) * WS_STRIDE + nb0 + nt * 8 + gid;
                b[nt][0] = bp[0];
                b[nt][1] = bp[4 * WS_STRIDE];
            }
            #pragma unroll
            for (int mt = 0; mt < 2; mt++)
                #pragma unroll
                for (int nt = 0; nt < 4; nt++)
                    mma_tf32(acc[mt][nt], a[mt][0], a[mt][1], a[mt][2], a[mt][3],
                             b[nt][0], b[nt][1]);
        }
    };

    // ---- QKV projections ----
    const float* Wptr[3] = {Wq, Wk, Wv};
    const float* bptr[3] = {bq, bk, bv};
    for (int g = 0; g < 3; g++) {
        __syncthreads();                 // Xs visible (g=0); prior gemm done reading Ws
        loadW(Wptr[g]);
        __syncthreads();                 // Ws visible
        float acc[2][4][4];
        gemm(Xs, acc);
        float* dst = qkv + g * 64 * XS_STRIDE;
        #pragma unroll
        for (int mt = 0; mt < 2; mt++) {
            #pragma unroll
            for (int nt = 0; nt < 4; nt++) {
                int r = warp_m * 32 + mt * 16 + gid;
                int c = warp_n * 32 + nt * 8 + tig * 2;
                float b0v = bptr[g][c], b1v = bptr[g][c + 1];
                dst[r * XS_STRIDE + c]            = acc[mt][nt][0] + b0v;
                dst[r * XS_STRIDE + c + 1]        = acc[mt][nt][1] + b1v;
                dst[(r + 8) * XS_STRIDE + c]      = acc[mt][nt][2] + b0v;
                dst[(r + 8) * XS_STRIDE + c + 1]  = acc[mt][nt][3] + b1v;
            }
        }
    }
    __syncthreads();                     // qkv visible; V-gemm done with Ws

    // ---- attention: one thread per (residue, head, query atom) ----
    {
        const int residue = tid >> 4;        // 0..15
        const int head    = (tid >> 2) & 3;  // 0..3
        const int qa      = tid & 3;         // 0..3
        const int d0      = head * 32;
        const int qrow    = residue * 4 + qa;

        const float* Q = qkv + 0 * 64 * XS_STRIDE;
        const float* K = qkv + 1 * 64 * XS_STRIDE;
        const float* V = qkv + 2 * 64 * XS_STRIDE;

        float4 qv[8];
        const float4* Qv = (const float4*)(Q + qrow * XS_STRIDE + d0);
        #pragma unroll
        for (int j = 0; j < 8; j++) qv[j] = Qv[j];

        float sc[4];
        int   vbit[4];
        int   nvalid = 0;
        #pragma unroll
        for (int e = 0; e < 4; e++) {
            vbit[e] = (mask[row0 + residue * 4 + e] != 0u) ? 1 : 0;
            nvalid += vbit[e];
            const float4* Kv = (const float4*)(K + (residue * 4 + e) * XS_STRIDE + d0);
            float s = 0.f;
            #pragma unroll
            for (int j = 0; j < 8; j++) {
                float4 kv = Kv[j];
                s += qv[j].x * kv.x + qv[j].y * kv.y + qv[j].z * kv.z + qv[j].w * kv.w;
            }
            sc[e] = vbit[e] ? s * 0.17677669529663687f : -1e30f;
        }
        float m = fmaxf(fmaxf(sc[0], sc[1]), fmaxf(sc[2], sc[3]));
        float p[4], psum = 0.f;
        #pragma unroll
        for (int e = 0; e < 4; e++) {
            p[e] = vbit[e] ? __expf(sc[e] - m) : 0.f;
            psum += p[e];
        }
        const float inv = (nvalid > 0) ? (1.f / psum) : 0.f;

        float4 c4[8];
        #pragma unroll
        for (int j = 0; j < 8; j++) c4[j] = make_float4(0.f, 0.f, 0.f, 0.f);
        #pragma unroll
        for (int e = 0; e < 4; e++) {
            const float4* Vv = (const float4*)(V + (residue * 4 + e) * XS_STRIDE + d0);
            float pe = p[e];
            #pragma unroll
            for (int j = 0; j < 8; j++) {
                float4 vv = Vv[j];
                c4[j].x += pe * vv.x; c4[j].y += pe * vv.y;
                c4[j].z += pe * vv.z; c4[j].w += pe * vv.w;
            }
        }
        uint4* ctx = (uint4*)(Xs + qrow * XS_STRIDE + d0);   // reuse Xs as ctx (tf32)
        #pragma unroll
        for (int j = 0; j < 8; j++) {
            uint4 u;
            u.x = f2tf(c4[j].x * inv); u.y = f2tf(c4[j].y * inv);
            u.z = f2tf(c4[j].z * inv); u.w = f2tf(c4[j].w * inv);
            ctx[j] = u;
        }
        if (head == 0 && qa == 0) resvl[residue] = (nvalid > 0) ? 1.f : 0.f;
    }

    loadW(Wo);
    __syncthreads();                     // ctx + Wo + resvl visible

    // ---- O projection + bias + residue zeroing -> global ----
    {
        float acc[2][4][4];
        gemm(Xs, acc);
        #pragma unroll
        for (int mt = 0; mt < 2; mt++) {
            #pragma unroll
            for (int nt = 0; nt < 4; nt++) {
                int r = warp_m * 32 + mt * 16 + gid;
                int c = warp_n * 32 + nt * 8 + tig * 2;
                float b0v = bo[c], b1v = bo[c + 1];
                float rm0 = resvl[r >> 2];
                float rm1 = resvl[(r + 8) >> 2];
                float2 v0 = make_float2((acc[mt][nt][0] + b0v) * rm0,
                                        (acc[mt][nt][1] + b1v) * rm0);
                float2 v1 = make_float2((acc[mt][nt][2] + b0v) * rm1,
                                        (acc[mt][nt][3] + b1v) * rm1);
                *(float2*)(out + (size_t)(row0 + r) * 128 + c)     = v0;
                *(float2*)(out + (size_t)(row0 + r + 8) * 128 + c) = v1;
            }
        }
    }
}

extern "C" void kernel_launch(void* const* d_in, const int* in_sizes, int n_in,
                              void* d_out, int out_size)
{
    const float*    x    = (const float*)d_in[0];
    const uint32_t* mask = (const uint32_t*)d_in[1];   // bool serialized 32-bit (f32 or i32): word != 0
    const float*    Wq   = (const float*)d_in[2];
    const float*    bq   = (const float*)d_in[3];
    const float*    Wk   = (const float*)d_in[4];
    const float*    bk   = (const float*)d_in[5];
    const float*    Wv   = (const float*)d_in[6];
    const float*    bv   = (const float*)d_in[7];
    const float*    Wo   = (const float*)d_in[8];
    const float*    bo   = (const float*)d_in[9];
    float* out = (float*)d_out;

    const int rows = in_sizes[0] / 128;   // B*L*A = 131072
    const int grid = rows / 64;           // 2048 CTAs

    cudaFuncSetAttribute(laa_kernel, cudaFuncAttributeMaxDynamicSharedMemorySize, SMEM_BYTES);
    laa_kernel<<<grid, 256, SMEM_BYTES>>>(x, mask, Wq, bq, Wk, bk, Wv, bv, Wo, bo, out);
}

// round 2
// speedup vs baseline: 1.4809x; 1.4809x over previous
#include <cuda_runtime.h>
#include <cstdint>

#define XS_STRIDE 132   // 128 + 4 pad (words) — LDSM phase conflict-free (528B mod 128 = 16)
#define WS_STRIDE 136   // 128 + 8 pad (words) — conflict-free scalar B loads

// smem byte offsets
#define OFF_XS   0                       // uint32 tf32, 64 x 132   (33792 B), reused as ctx
#define OFF_QKV  33792                   // float,       3 x 64 x 132 (101376 B)
#define OFF_WS   135168                  // uint32 tf32, 128 x 136  (69632 B)
#define OFF_MS   204800                  // uint32 mask words, 64   (256 B)
#define OFF_RV   205056                  // float, 16 residue-valid flags
#define SMEM_BYTES 205120

__device__ __forceinline__ uint32_t f2tf(float f) {
    uint32_t r;
    asm("cvt.rna.tf32.f32 %0, %1;" : "=r"(r) : "f"(f));
    return r;
}

__device__ __forceinline__ void mma_tf32(float* d,
                                         uint32_t a0, uint32_t a1, uint32_t a2, uint32_t a3,
                                         uint32_t b0, uint32_t b1) {
    asm volatile(
        "mma.sync.aligned.m16n8k8.row.col.f32.tf32.tf32.f32 "
        "{%0,%1,%2,%3}, {%4,%5,%6,%7}, {%8,%9}, {%0,%1,%2,%3};\n"
        : "+f"(d[0]), "+f"(d[1]), "+f"(d[2]), "+f"(d[3])
        : "r"(a0), "r"(a1), "r"(a2), "r"(a3), "r"(b0), "r"(b1));
}

__device__ __forceinline__ void ldsm_x4(uint32_t& r0, uint32_t& r1, uint32_t& r2,
                                        uint32_t& r3, uint32_t saddr) {
    asm volatile("ldmatrix.sync.aligned.m8n8.x4.shared.b16 {%0,%1,%2,%3}, [%4];"
                 : "=r"(r0), "=r"(r1), "=r"(r2), "=r"(r3) : "r"(saddr));
}

__global__ __launch_bounds__(512, 1)
void laa_kernel(const float* __restrict__ x, const uint32_t* __restrict__ mask,
                const float* __restrict__ Wq, const float* __restrict__ bq,
                const float* __restrict__ Wk, const float* __restrict__ bk,
                const float* __restrict__ Wv, const float* __restrict__ bv,
                const float* __restrict__ Wo, const float* __restrict__ bo,
                float* __restrict__ out)
{
    extern __shared__ char smem[];
    uint32_t* Xs    = (uint32_t*)(smem + OFF_XS);
    float*    qkv   = (float*)   (smem + OFF_QKV);
    uint32_t* Ws    = (uint32_t*)(smem + OFF_WS);
    uint32_t* maskS = (uint32_t*)(smem + OFF_MS);
    float*    resvl = (float*)   (smem + OFF_RV);

    const int tid    = threadIdx.x;
    const int lane   = tid & 31;
    const int warp   = tid >> 5;    // 0..15
    const int gid    = lane >> 2;   // 0..7
    const int tig    = lane & 3;    // 0..3
    const int warp_m = warp >> 2;   // 0..3 (16-row slabs)
    const int warp_n = warp & 3;    // 0..3 (32-col slabs)
    const int row0   = blockIdx.x * 64;

    // ---- load X tile (64x128 fp32) -> Xs as tf32; mask words -> smem ----
    #pragma unroll
    for (int i = 0; i < 4; i++) {
        int fi = tid + i * 512;          // 0..2047 float4 slots
        int r  = fi >> 5;
        int c4 = fi & 31;
        float4 v = *(const float4*)(x + (size_t)(row0 + r) * 128 + c4 * 4);
        uint32_t* dst = Xs + r * XS_STRIDE + c4 * 4;
        dst[0] = f2tf(v.x); dst[1] = f2tf(v.y); dst[2] = f2tf(v.z); dst[3] = f2tf(v.w);
    }
    if (tid < 64) maskS[tid] = mask[row0 + tid];

    // per-thread A ldmatrix base (always reads from Xs)
    const int a_row = warp_m * 16 + (lane & 7) + (lane & 8);
    const int a_col = ((lane >> 4) & 1) * 4;
    const uint32_t a_base =
        (uint32_t)__cvta_generic_to_shared(Xs + a_row * XS_STRIDE + a_col);

    // GEMM: acc[4][4] = Xs(64x128 tf32) @ Ws(128x128 tf32), warp tile 16x32
    auto gemm = [&](float acc[4][4]) {
        #pragma unroll
        for (int nt = 0; nt < 4; nt++)
            #pragma unroll
            for (int j = 0; j < 4; j++) acc[nt][j] = 0.f;
        #pragma unroll
        for (int kk = 0; kk < 16; kk++) {
            const int k0 = kk * 8;
            uint32_t a0, a1, a2, a3;
            ldsm_x4(a0, a1, a2, a3, a_base + (uint32_t)(k0 * 4));
            const uint32_t* bp = Ws + (k0 + tig) * WS_STRIDE + warp_n * 32 + gid;
            uint32_t b[4][2];
            #pragma unroll
            for (int nt = 0; nt < 4; nt++) {
                b[nt][0] = bp[nt * 8];
                b[nt][1] = bp[4 * WS_STRIDE + nt * 8];
            }
            #pragma unroll
            for (int nt = 0; nt < 4; nt++)
                mma_tf32(acc[nt], a0, a1, a2, a3, b[nt][0], b[nt][1]);
        }
    };

    // ---- prefetch Wq into registers ----
    float4 p[8];
    #pragma unroll
    for (int i = 0; i < 8; i++) {
        int fi = tid + i * 512;          // 0..4095 float4 slots
        p[i] = *(const float4*)(Wq + (fi >> 5) * 128 + (fi & 31) * 4);
    }

    const float* Wnext[3] = {Wk, Wv, Wo};
    const float* bptr[3]  = {bq, bk, bv};

    // ---- QKV projections (prefetch next W during current GEMM) ----
    for (int g = 0; g < 3; g++) {
        // stage prefetched W -> Ws as tf32
        #pragma unroll
        for (int i = 0; i < 8; i++) {
            int fi = tid + i * 512;
            uint32_t* dst = Ws + (fi >> 5) * WS_STRIDE + (fi & 31) * 4;
            dst[0] = f2tf(p[i].x); dst[1] = f2tf(p[i].y);
            dst[2] = f2tf(p[i].z); dst[3] = f2tf(p[i].w);
        }
        // prefetch next W (in flight during this GEMM)
        const float* Wn = Wnext[g];
        #pragma unroll
        for (int i = 0; i < 8; i++) {
            int fi = tid + i * 512;
            p[i] = *(const float4*)(Wn + (fi >> 5) * 128 + (fi & 31) * 4);
        }
        __syncthreads();                 // Xs (g=0) + Ws visible

        float acc[4][4];
        gemm(acc);

        float* dst = qkv + g * 64 * XS_STRIDE;
        const int r = warp_m * 16 + gid;
        #pragma unroll
        for (int nt = 0; nt < 4; nt++) {
            int c = warp_n * 32 + nt * 8 + tig * 2;
            float b0v = __ldg(bptr[g] + c), b1v = __ldg(bptr[g] + c + 1);
            dst[r * XS_STRIDE + c]           = acc[nt][0] + b0v;
            dst[r * XS_STRIDE + c + 1]       = acc[nt][1] + b1v;
            dst[(r + 8) * XS_STRIDE + c]     = acc[nt][2] + b0v;
            dst[(r + 8) * XS_STRIDE + c + 1] = acc[nt][3] + b1v;
        }
        __syncthreads();                 // Ws free; qkv[g] visible
    }

    // ---- stage Wo (prefetched) -> Ws; runs concurrently with attention ----
    #pragma unroll
    for (int i = 0; i < 8; i++) {
        int fi = tid + i * 512;
        uint32_t* dst = Ws + (fi >> 5) * WS_STRIDE + (fi & 31) * 4;
        dst[0] = f2tf(p[i].x); dst[1] = f2tf(p[i].y);
        dst[2] = f2tf(p[i].z); dst[3] = f2tf(p[i].w);
    }

    // ---- attention: one thread per (residue, head, query atom), tid < 256 ----
    if (tid < 256) {
        const int residue = tid >> 4;
        const int head    = (tid >> 2) & 3;
        const int qa      = tid & 3;
        const int d0      = head * 32;
        const int qrow    = residue * 4 + qa;

        const float* Q = qkv + 0 * 64 * XS_STRIDE;
        const float* K = qkv + 1 * 64 * XS_STRIDE;
        const float* V = qkv + 2 * 64 * XS_STRIDE;

        float4 qv[8];
        const float4* Qv = (const float4*)(Q + qrow * XS_STRIDE + d0);
        #pragma unroll
        for (int j = 0; j < 8; j++) qv[j] = Qv[j];

        float sc[4];
        int   vbit[4];
        int   nvalid = 0;
        #pragma unroll
        for (int e = 0; e < 4; e++) {
            vbit[e] = (maskS[residue * 4 + e] != 0u) ? 1 : 0;
            nvalid += vbit[e];
            const float4* Kv = (const float4*)(K + (residue * 4 + e) * XS_STRIDE + d0);
            float s = 0.f;
            #pragma unroll
            for (int j = 0; j < 8; j++) {
                float4 kv = Kv[j];
                s += qv[j].x * kv.x + qv[j].y * kv.y + qv[j].z * kv.z + qv[j].w * kv.w;
            }
            sc[e] = vbit[e] ? s * 0.17677669529663687f : -1e30f;
        }
        float m = fmaxf(fmaxf(sc[0], sc[1]), fmaxf(sc[2], sc[3]));
        float pb[4], psum = 0.f;
        #pragma unroll
        for (int e = 0; e < 4; e++) {
            pb[e] = vbit[e] ? __expf(sc[e] - m) : 0.f;
            psum += pb[e];
        }
        const float inv = (nvalid > 0) ? (1.f / psum) : 0.f;

        float4 c4[8];
        #pragma unroll
        for (int j = 0; j < 8; j++) c4[j] = make_float4(0.f, 0.f, 0.f, 0.f);
        #pragma unroll
        for (int e = 0; e < 4; e++) {
            const float4* Vv = (const float4*)(V + (residue * 4 + e) * XS_STRIDE + d0);
            float pe = pb[e];
            #pragma unroll
            for (int j = 0; j < 8; j++) {
                float4 vv = Vv[j];
                c4[j].x += pe * vv.x; c4[j].y += pe * vv.y;
                c4[j].z += pe * vv.z; c4[j].w += pe * vv.w;
            }
        }
        uint4* ctx = (uint4*)(Xs + qrow * XS_STRIDE + d0);   // reuse Xs as ctx (tf32)
        #pragma unroll
        for (int j = 0; j < 8; j++) {
            uint4 u;
            u.x = f2tf(c4[j].x * inv); u.y = f2tf(c4[j].y * inv);
            u.z = f2tf(c4[j].z * inv); u.w = f2tf(c4[j].w * inv);
            ctx[j] = u;
        }
        if (head == 0 && qa == 0) resvl[residue] = (nvalid > 0) ? 1.f : 0.f;
    }
    __syncthreads();                     // ctx + Wo + resvl visible

    // ---- O projection + bias + residue zeroing -> global ----
    {
        float acc[4][4];
        gemm(acc);
        const int r = warp_m * 16 + gid;
        const float rm0 = resvl[r >> 2];
        const float rm1 = resvl[(r + 8) >> 2];
        #pragma unroll
        for (int nt = 0; nt < 4; nt++) {
            int c = warp_n * 32 + nt * 8 + tig * 2;
            float b0v = __ldg(bo + c), b1v = __ldg(bo + c + 1);
            float2 v0 = make_float2((acc[nt][0] + b0v) * rm0,
                                    (acc[nt][1] + b1v) * rm0);
            float2 v1 = make_float2((acc[nt][2] + b0v) * rm1,
                                    (acc[nt][3] + b1v) * rm1);
            *(float2*)(out + (size_t)(row0 + r) * 128 + c)     = v0;
            *(float2*)(out + (size_t)(row0 + r + 8) * 128 + c) = v1;
        }
    }
}

extern "C" void kernel_launch(void* const* d_in, const int* in_sizes, int n_in,
                              void* d_out, int out_size)
{
    const float*    x    = (const float*)d_in[0];
    const uint32_t* mask = (const uint32_t*)d_in[1];
    const float*    Wq   = (const float*)d_in[2];
    const float*    bq   = (const float*)d_in[3];
    const float*    Wk   = (const float*)d_in[4];
    const float*    bk   = (const float*)d_in[5];
    const float*    Wv   = (const float*)d_in[6];
    const float*    bv   = (const float*)d_in[7];
    const float*    Wo   = (const float*)d_in[8];
    const float*    bo   = (const float*)d_in[9];
    float* out = (float*)d_out;

    const int rows = in_sizes[0] / 128;   // B*L*A = 131072
    const int grid = rows / 64;           // 2048 CTAs

    cudaFuncSetAttribute(laa_kernel, cudaFuncAttributeMaxDynamicSharedMemorySize, SMEM_BYTES);
    laa_kernel<<<grid, 512, SMEM_BYTES>>>(x, mask, Wq, bq, Wk, bk, Wv, bv, Wo, bo, out);
}

// round 4
// speedup vs baseline: 2.0966x; 1.4157x over previous
#include <cuda_runtime.h>
#include <cstdint>

#define XS_STRIDE 132   // words: 128 + 4 pad — conflict-free ldmatrix
#define WS_STRIDE 136   // words: 128 + 8 pad — conflict-free scalar B loads

// smem byte offsets
#define OFF_A   0         // X tile / ctx: 128 x 132 tf32 words (67584 B)
#define OFF_B0  67584     // W buffer 0:   128 x 136 words (69632 B)
#define OFF_B1  137216    // W buffer 1:   128 x 136 words (69632 B)
#define OFF_MS  206848    // 128 mask words (512 B)
#define SMEM_BYTES 207360

static __device__ __forceinline__ uint32_t f2tf(float f) {
    uint32_t r; asm("cvt.rna.tf32.f32 %0, %1;" : "=r"(r) : "f"(f)); return r;
}

static __device__ __forceinline__ void mma_tf32(float* d,
        uint32_t a0, uint32_t a1, uint32_t a2, uint32_t a3,
        uint32_t b0, uint32_t b1) {
    asm volatile(
        "mma.sync.aligned.m16n8k8.row.col.f32.tf32.tf32.f32 "
        "{%0,%1,%2,%3}, {%4,%5,%6,%7}, {%8,%9}, {%0,%1,%2,%3};\n"
        : "+f"(d[0]), "+f"(d[1]), "+f"(d[2]), "+f"(d[3])
        : "r"(a0), "r"(a1), "r"(a2), "r"(a3), "r"(b0), "r"(b1));
}

static __device__ __forceinline__ void ldsm_x4(uint32_t& r0, uint32_t& r1,
        uint32_t& r2, uint32_t& r3, uint32_t saddr) {
    asm volatile("ldmatrix.sync.aligned.m8n8.x4.shared.b16 {%0,%1,%2,%3}, [%4];"
                 : "=r"(r0), "=r"(r1), "=r"(r2), "=r"(r3) : "r"(saddr));
}

__global__ __launch_bounds__(512, 1)
void laa_kernel(const float* __restrict__ x, const uint32_t* __restrict__ mask,
                const float* __restrict__ Wq, const float* __restrict__ bq,
                const float* __restrict__ Wk, const float* __restrict__ bk,
                const float* __restrict__ Wv, const float* __restrict__ bv,
                const float* __restrict__ Wo, const float* __restrict__ bo,
                float* __restrict__ out)
{
    extern __shared__ char smem[];
    uint32_t* Xs    = (uint32_t*)(smem + OFF_A);
    uint32_t* Bs0   = (uint32_t*)(smem + OFF_B0);
    uint32_t* Bs1   = (uint32_t*)(smem + OFF_B1);
    uint32_t* maskS = (uint32_t*)(smem + OFF_MS);

    const int tid  = threadIdx.x;
    const int lane = tid & 31;
    const int w    = tid >> 5;     // 0..15
    const int gid  = lane >> 2;    // 0..7
    const int tig  = lane & 3;     // 0..3
    const int wm   = w >> 2;       // row group: rows 32*wm..
    const int wn   = w & 3;        // col slab = head wn
    const int row0 = blockIdx.x * 128;

    // ---- stage X tile (128x128 f32 -> tf32) ----
    #pragma unroll
    for (int i = 0; i < 8; i++) {
        int fi = tid + i * 512;              // 0..4095 float4 slots
        int r = fi >> 5, c4 = fi & 31;
        float4 v = *(const float4*)(x + (size_t)(row0 + r) * 128 + c4 * 4);
        uint4 u; u.x = f2tf(v.x); u.y = f2tf(v.y); u.z = f2tf(v.z); u.w = f2tf(v.w);
        *(uint4*)(Xs + r * XS_STRIDE + c4 * 4) = u;
    }
    // ---- stage W (row-major k x n, f32 -> tf32) ----
    auto stageW = [&](const float* __restrict__ W, uint32_t* Ws) {
        #pragma unroll
        for (int i = 0; i < 8; i++) {
            int fi = tid + i * 512;
            int r = fi >> 5, c4 = fi & 31;
            float4 v = *(const float4*)(W + r * 128 + c4 * 4);
            uint4 u; u.x = f2tf(v.x); u.y = f2tf(v.y); u.z = f2tf(v.z); u.w = f2tf(v.w);
            *(uint4*)(Ws + r * WS_STRIDE + c4 * 4) = u;
        }
    };
    stageW(Wq, Bs0);
    stageW(Wk, Bs1);
    if (tid < 128) maskS[tid] = mask[row0 + tid];
    __syncthreads();

    // ldmatrix bases for the two 16-row m-fragments of this warp's 32-row slab
    const int a_row = wm * 32 + (lane & 15);
    const uint32_t a_base0 =
        (uint32_t)__cvta_generic_to_shared(Xs + a_row * XS_STRIDE + ((lane >> 4) & 1) * 4);
    const uint32_t a_base1 = a_base0 + 16 * XS_STRIDE * 4;

    // GEMM: acc[2][4][4] (+=) = Xs(128x128) @ Ws(128x128); warp tile 32x32
    auto gemm = [&](float acc[2][4][4], const uint32_t* Ws) {
        #pragma unroll
        for (int mf = 0; mf < 2; mf++)
            #pragma unroll
            for (int n = 0; n < 4; n++)
                #pragma unroll
                for (int j = 0; j < 4; j++) acc[mf][n][j] = 0.f;
        #pragma unroll
        for (int kk = 0; kk < 16; kk++) {
            const int k0 = kk * 8;
            uint32_t a0[2], a1[2], a2[2], a3[2];
            ldsm_x4(a0[0], a1[0], a2[0], a3[0], a_base0 + (uint32_t)(k0 * 4));
            ldsm_x4(a0[1], a1[1], a2[1], a3[1], a_base1 + (uint32_t)(k0 * 4));
            const uint32_t* bp = Ws + (k0 + tig) * WS_STRIDE + wn * 32 + gid;
            uint32_t b[4][2];
            #pragma unroll
            for (int n = 0; n < 4; n++) {
                b[n][0] = bp[n * 8];
                b[n][1] = bp[4 * WS_STRIDE + n * 8];
            }
            #pragma unroll
            for (int mf = 0; mf < 2; mf++)
                #pragma unroll
                for (int n = 0; n < 4; n++)
                    mma_tf32(acc[mf][n], a0[mf], a1[mf], a2[mf], a3[mf],
                             b[n][0], b[n][1]);
        }
    };

    const int colb = wn * 32 + 2 * tig;   // + n*8 per n-frag; cols (colb, colb+1)

    float P[2][2][4];     // attention weights per (mf, half, key atom)
    float rv[2][2];       // residue-valid flag per (mf, half)
    {
        // ---- Q, K GEMMs (QKV stay in registers) ----
        float Qa[2][4][4], Ka[2][4][4];
        gemm(Qa, Bs0);
        gemm(Ka, Bs1);
        #pragma unroll
        for (int n = 0; n < 4; n++) {
            float2 b2q = __ldg((const float2*)(bq + colb + n * 8));
            float2 b2k = __ldg((const float2*)(bk + colb + n * 8));
            #pragma unroll
            for (int mf = 0; mf < 2; mf++) {
                Qa[mf][n][0] += b2q.x; Qa[mf][n][1] += b2q.y;
                Qa[mf][n][2] += b2q.x; Qa[mf][n][3] += b2q.y;
                Ka[mf][n][0] += b2k.x; Ka[mf][n][1] += b2k.y;
                Ka[mf][n][2] += b2k.x; Ka[mf][n][3] += b2k.y;
            }
        }

        // ---- scores + softmax, all in registers via shuffles ----
        #pragma unroll
        for (int mf = 0; mf < 2; mf++) {
            #pragma unroll
            for (int half = 0; half < 2; half++) {
                const int rowg = wm * 32 + mf * 16 + half * 8 + gid;
                const int rb   = rowg & ~3;
                float vb[4], sc[4];
                #pragma unroll
                for (int e = 0; e < 4; e++)
                    vb[e] = (maskS[rb | e] != 0u) ? 1.f : 0.f;
                #pragma unroll
                for (int e = 0; e < 4; e++) {
                    const int src = (lane & ~12) | (e << 2);
                    float s = 0.f;
                    #pragma unroll
                    for (int n = 0; n < 4; n++) {
                        #pragma unroll
                        for (int dj = 0; dj < 2; dj++) {
                            int j = half * 2 + dj;
                            s = fmaf(Qa[mf][n][j],
                                     __shfl_sync(0xffffffffu, Ka[mf][n][j], src), s);
                        }
                    }
                    s += __shfl_xor_sync(0xffffffffu, s, 1);
                    s += __shfl_xor_sync(0xffffffffu, s, 2);
                    sc[e] = (vb[e] > 0.f) ? s * 0.17677669529663687f : -1e30f;
                }
                float mx = fmaxf(fmaxf(sc[0], sc[1]), fmaxf(sc[2], sc[3]));
                float ps = 0.f, pe[4];
                #pragma unroll
                for (int e = 0; e < 4; e++) {
                    pe[e] = (vb[e] > 0.f) ? __expf(sc[e] - mx) : 0.f;
                    ps += pe[e];
                }
                float any = vb[0] + vb[1] + vb[2] + vb[3];
                float inv = (any > 0.f) ? (1.f / ps) : 0.f;
                rv[mf][half] = (any > 0.f) ? 1.f : 0.f;
                #pragma unroll
                for (int e = 0; e < 4; e++) P[mf][half][e] = pe[e] * inv;
            }
        }
    }   // Qa, Ka dead

    __syncthreads();            // all warps done with Bs0/Bs1
    stageW(Wv, Bs0);
    stageW(Wo, Bs1);
    __syncthreads();

    // ---- V GEMM + P·V (registers) ----
    float cx[2][4][4];
    {
        float Va[2][4][4];
        gemm(Va, Bs0);
        #pragma unroll
        for (int n = 0; n < 4; n++) {
            float2 b2v = __ldg((const float2*)(bv + colb + n * 8));
            #pragma unroll
            for (int mf = 0; mf < 2; mf++) {
                Va[mf][n][0] += b2v.x; Va[mf][n][1] += b2v.y;
                Va[mf][n][2] += b2v.x; Va[mf][n][3] += b2v.y;
            }
        }
        #pragma unroll
        for (int mf = 0; mf < 2; mf++)
            #pragma unroll
            for (int n = 0; n < 4; n++)
                #pragma unroll
                for (int j = 0; j < 4; j++) cx[mf][n][j] = 0.f;
        #pragma unroll
        for (int mf = 0; mf < 2; mf++) {
            #pragma unroll
            for (int half = 0; half < 2; half++) {
                #pragma unroll
                for (int e = 0; e < 4; e++) {
                    const int src = (lane & ~12) | (e << 2);
                    const float pw = P[mf][half][e];
                    #pragma unroll
                    for (int n = 0; n < 4; n++) {
                        #pragma unroll
                        for (int dj = 0; dj < 2; dj++) {
                            int j = half * 2 + dj;
                            cx[mf][n][j] = fmaf(pw,
                                __shfl_sync(0xffffffffu, Va[mf][n][j], src),
                                cx[mf][n][j]);
                        }
                    }
                }
            }
        }
    }   // Va dead

    __syncthreads();            // all warps done reading Xs (V GEMM)

    // ---- ctx -> Xs (tf32), rows rowg, cols = this head's slab ----
    #pragma unroll
    for (int mf = 0; mf < 2; mf++) {
        #pragma unroll
        for (int half = 0; half < 2; half++) {
            const int rowg = wm * 32 + mf * 16 + half * 8 + gid;
            #pragma unroll
            for (int n = 0; n < 4; n++) {
                uint2 u;
                u.x = f2tf(cx[mf][n][half * 2 + 0]);
                u.y = f2tf(cx[mf][n][half * 2 + 1]);
                *(uint2*)(Xs + rowg * XS_STRIDE + colb + n * 8) = u;
            }
        }
    }
    __syncthreads();

    // ---- O GEMM + bias + residue zeroing -> global ----
    {
        float Oa[2][4][4];
        gemm(Oa, Bs1);
        #pragma unroll
        for (int mf = 0; mf < 2; mf++) {
            #pragma unroll
            for (int half = 0; half < 2; half++) {
                const int rowg = wm * 32 + mf * 16 + half * 8 + gid;
                const float r = rv[mf][half];
                #pragma unroll
                for (int n = 0; n < 4; n++) {
                    float2 b2o = __ldg((const float2*)(bo + colb + n * 8));
                    float2 o;
                    o.x = (Oa[mf][n][half * 2 + 0] + b2o.x) * r;
                    o.y = (Oa[mf][n][half * 2 + 1] + b2o.y) * r;
                    *(float2*)(out + (size_t)(row0 + rowg) * 128 + colb + n * 8) = o;
                }
            }
        }
    }
}

extern "C" void kernel_launch(void* const* d_in, const int* in_sizes, int n_in,
                              void* d_out, int out_size)
{
    const float*    x    = (const float*)d_in[0];
    const uint32_t* mask = (const uint32_t*)d_in[1];
    const float*    Wq   = (const float*)d_in[2];
    const float*    bq   = (const float*)d_in[3];
    const float*    Wk   = (const float*)d_in[4];
    const float*    bk   = (const float*)d_in[5];
    const float*    Wv   = (const float*)d_in[6];
    const float*    bv   = (const float*)d_in[7];
    const float*    Wo   = (const float*)d_in[8];
    const float*    bo   = (const float*)d_in[9];
    float* out = (float*)d_out;

    const int rows = in_sizes[0] / 128;   // 131072
    const int grid = rows / 128;          // 1024

    cudaFuncSetAttribute(laa_kernel, cudaFuncAttributeMaxDynamicSharedMemorySize, SMEM_BYTES);
    laa_kernel<<<grid, 512, SMEM_BYTES>>>(x, mask, Wq, bq, Wk, bk, Wv, bv, Wo, bo, out);
}